// round 1
// baseline (speedup 1.0000x reference)
#include <cuda_runtime.h>
#include <cstdint>

#define BMAX 524288
#define NPART 148

// ---------------- static device scratch (no allocations) ----------------
__device__ float  g_C[136 * 12];          // quadratic-form coeffs, [pair][f]
__device__ float  g_q[(size_t)12 * BMAX]; // per-sample features, SoA [f][b]
__device__ double g_part[NPART * 90];     // per-block stat partials
__device__ float  g_A[128 * 12];          // fused FC+BN scale
__device__ float  g_cc[128];              // fused FC+BN shift

// ---------------- small complex helpers for circuit build ----------------
__device__ __forceinline__ void apply1(float2* amp, int q,
                                       float2 g00, float2 g01,
                                       float2 g10, float2 g11) {
    int bit = 8 >> q; // wire 0 = MSB of 4-bit index
    #pragma unroll
    for (int k = 0; k < 16; k++) {
        if (!(k & bit)) {
            float2 a0 = amp[k], a1 = amp[k | bit];
            amp[k] = make_float2(
                g00.x * a0.x - g00.y * a0.y + g01.x * a1.x - g01.y * a1.y,
                g00.x * a0.y + g00.y * a0.x + g01.x * a1.y + g01.y * a1.x);
            amp[k | bit] = make_float2(
                g10.x * a0.x - g10.y * a0.y + g11.x * a1.x - g11.y * a1.y,
                g10.x * a0.y + g10.y * a0.x + g11.x * a1.y + g11.y * a1.x);
        }
    }
}

__device__ __forceinline__ void cnot_g(float2* amp, int q1, int q2) {
    int b1 = 8 >> q1, b2 = 8 >> q2;
    #pragma unroll
    for (int k = 0; k < 16; k++) {
        if ((k & b1) && !(k & b2)) {
            float2 t = amp[k];
            amp[k] = amp[k | b2];
            amp[k | b2] = t;
        }
    }
}

__device__ __forceinline__ void cz_g(float2* amp, int q1, int q2) {
    int b1 = 8 >> q1, b2 = 8 >> q2;
    #pragma unroll
    for (int k = 0; k < 16; k++) {
        if ((k & b1) && (k & b2)) {
            amp[k].x = -amp[k].x;
            amp[k].y = -amp[k].y;
        }
    }
}

// ---------------- kernel 1: build U matrices + quadratic-form coeffs ----
__global__ void build_kernel(const float* __restrict__ p1,
                             const float* __restrict__ p2,
                             const float* __restrict__ p3) {
    __shared__ float2 sU[3][16][16]; // [circuit][row k][col t]
    const float INVS = 0.7071067811865476f;
    int tid = threadIdx.x;

    if (tid < 48) {
        int c = tid >> 4, t = tid & 15;
        const float* P = (c == 0) ? p1 : ((c == 1) ? p2 : p3);
        float2 amp[16];
        #pragma unroll
        for (int k = 0; k < 16; k++) amp[k] = make_float2(0.f, 0.f);
        amp[t] = make_float2(1.f, 0.f);

        for (int l = 0; l < 2; l++) {
            const float* pl = P + l * 12;
            // H on every qubit
            for (int i = 0; i < 4; i++)
                apply1(amp, i, make_float2(INVS, 0), make_float2(INVS, 0),
                       make_float2(INVS, 0), make_float2(-INVS, 0));
            // RY, RZ, RX per qubit
            for (int i = 0; i < 4; i++) {
                float th = pl[i] * 0.5f;
                float cy = cosf(th), sy = sinf(th);
                apply1(amp, i, make_float2(cy, 0), make_float2(-sy, 0),
                       make_float2(sy, 0), make_float2(cy, 0));
                th = pl[4 + i] * 0.5f;
                float cz = cosf(th), sz = sinf(th);
                apply1(amp, i, make_float2(cz, -sz), make_float2(0, 0),
                       make_float2(0, 0), make_float2(cz, sz));
                th = pl[8 + i] * 0.5f;
                float cx = cosf(th), sx = sinf(th);
                apply1(amp, i, make_float2(cx, 0), make_float2(0, -sx),
                       make_float2(0, -sx), make_float2(cx, 0));
            }
            // S on every qubit
            for (int i = 0; i < 4; i++) {
                int bit = 8 >> i;
                for (int k = 0; k < 16; k++)
                    if (k & bit) {
                        float r = amp[k].x;
                        amp[k].x = -amp[k].y;
                        amp[k].y = r;
                    }
            }
            // entangling ring
            for (int i = 0; i < 3; i++) { cnot_g(amp, i, i + 1); cz_g(amp, i, i + 1); }
            cnot_g(amp, 3, 0);
            cz_g(amp, 3, 0);
        }
        for (int k = 0; k < 16; k++) sU[c][k][t] = amp[k];
    }
    __syncthreads();

    // A_f = Re(U^H D_f U); with x real only the symmetric real part matters.
    // Fold into upper-triangle coeffs (off-diagonals doubled).
    for (int e = tid; e < 1632; e += blockDim.x) {
        int f = e % 12, pr = e / 12;
        int i = 0, rem = pr;
        while (rem >= 16 - i) { rem -= 16 - i; i++; }
        int j = i + rem;
        int c = f >> 2, i0 = f & 3;
        int bit = 8 >> i0;
        float m = 0.f;
        for (int k = 0; k < 16; k++) {
            float2 ui = sU[c][k][i], uj = sU[c][k][j];
            float d = (k & bit) ? -1.f : 1.f;
            m += d * (ui.x * uj.x + ui.y * uj.y);
        }
        g_C[pr * 12 + f] = (i == j) ? m : 2.f * m;
    }
}

// ---------------- kernel 2: per-sample quadratic forms -> q[12] ---------
__global__ void qforms_kernel(const float* __restrict__ x, int B) {
    __shared__ float sC[1632];
    for (int e = threadIdx.x; e < 1632; e += blockDim.x) sC[e] = g_C[e];
    __syncthreads();

    int stride = gridDim.x * blockDim.x;
    for (int b = blockIdx.x * blockDim.x + threadIdx.x; b < B; b += stride) {
        const float4* xp = reinterpret_cast<const float4*>(x) + (size_t)b * 4;
        float xv[16];
        float4 v;
        v = xp[0]; xv[0]  = v.x; xv[1]  = v.y; xv[2]  = v.z; xv[3]  = v.w;
        v = xp[1]; xv[4]  = v.x; xv[5]  = v.y; xv[6]  = v.z; xv[7]  = v.w;
        v = xp[2]; xv[8]  = v.x; xv[9]  = v.y; xv[10] = v.z; xv[11] = v.w;
        v = xp[3]; xv[12] = v.x; xv[13] = v.y; xv[14] = v.z; xv[15] = v.w;

        float n2 = 0.f;
        #pragma unroll
        for (int i = 0; i < 16; i++) n2 = fmaf(xv[i], xv[i], n2);
        float inv = 1.0f / n2;

        float q[12];
        #pragma unroll
        for (int f = 0; f < 12; f++) q[f] = 0.f;

        #pragma unroll
        for (int i = 0; i < 16; i++) {
            #pragma unroll
            for (int j = i; j < 16; j++) {
                float pv = xv[i] * xv[j];
                const int pr = i * 16 - (i * (i - 1)) / 2 + (j - i);
                #pragma unroll
                for (int f = 0; f < 12; f++)
                    q[f] = fmaf(sC[pr * 12 + f], pv, q[f]);
            }
        }
        #pragma unroll
        for (int f = 0; f < 12; f++)
            g_q[(size_t)f * B + b] = q[f] * inv;
    }
}

// ---------------- kernel 3: batch moments (deterministic tree) ----------
__global__ void stats_kernel(int B) {
    float acc[90];
    #pragma unroll
    for (int k = 0; k < 90; k++) acc[k] = 0.f;

    int stride = gridDim.x * blockDim.x;
    for (int b = blockIdx.x * blockDim.x + threadIdx.x; b < B; b += stride) {
        float qv[12];
        #pragma unroll
        for (int f = 0; f < 12; f++) qv[f] = g_q[(size_t)f * B + b];
        #pragma unroll
        for (int f = 0; f < 12; f++) acc[f] += qv[f];
        int k = 12;
        #pragma unroll
        for (int f = 0; f < 12; f++)
            #pragma unroll
            for (int g = f; g < 12; g++)
                acc[k++] += qv[f] * qv[g];
    }
    // warp reduce each of the 90
    #pragma unroll
    for (int k = 0; k < 90; k++)
        #pragma unroll
        for (int off = 16; off > 0; off >>= 1)
            acc[k] += __shfl_down_sync(0xffffffffu, acc[k], off);

    __shared__ float swarp[8][90];
    int warp = threadIdx.x >> 5, lane = threadIdx.x & 31;
    if (lane == 0)
        for (int k = 0; k < 90; k++) swarp[warp][k] = acc[k];
    __syncthreads();

    int nw = blockDim.x >> 5;
    for (int k = threadIdx.x; k < 90; k += blockDim.x) {
        double s = 0.0;
        for (int w = 0; w < nw; w++) s += (double)swarp[w][k];
        g_part[blockIdx.x * 90 + k] = s;
    }
}

// ---------------- kernel 4: fold BN into affine coeffs ------------------
__global__ void coef_kernel(const float* __restrict__ fw,
                            const float* __restrict__ fb,
                            const float* __restrict__ gamma,
                            const float* __restrict__ beta,
                            int B, int npart) {
    __shared__ double ss[90];
    for (int k = threadIdx.x; k < 90; k += blockDim.x) {
        double s = 0.0;
        for (int p = 0; p < npart; p++) s += g_part[p * 90 + k];
        ss[k] = s;
    }
    __syncthreads();

    int j = threadIdx.x;
    if (j < 128) {
        double invB = 1.0 / (double)B;
        double mean[12], w[12];
        for (int f = 0; f < 12; f++) {
            mean[f] = ss[f] * invB;
            w[f] = (double)fw[j * 12 + f];
        }
        double mu = (double)fb[j];
        for (int f = 0; f < 12; f++) mu += w[f] * mean[f];
        double var = 0.0;
        for (int f = 0; f < 12; f++)
            for (int g = 0; g < 12; g++) {
                int a = f < g ? f : g, bb = f < g ? g : f;
                double e2 = ss[12 + a * 12 - (a * (a + 1)) / 2 + bb] * invB;
                var += w[f] * w[g] * (e2 - mean[f] * mean[g]);
            }
        double s = (double)gamma[j] * rsqrt(var + 1e-5);
        for (int f = 0; f < 12; f++) g_A[j * 12 + f] = (float)(s * w[f]);
        g_cc[j] = (float)(s * ((double)fb[j] - mu) + (double)beta[j]);
    }
}

// ---------------- kernel 5: fused FC+BN+ReLU output ---------------------
__global__ void out_kernel(float* __restrict__ out, int B) {
    int lane = threadIdx.x & 31;
    int gw = (blockIdx.x * blockDim.x + threadIdx.x) >> 5;
    int nw = (gridDim.x * blockDim.x) >> 5;
    int j0 = lane * 4;

    float a[4][12], cc[4];
    #pragma unroll
    for (int u = 0; u < 4; u++) {
        cc[u] = g_cc[j0 + u];
        #pragma unroll
        for (int f = 0; f < 12; f++) a[u][f] = g_A[(j0 + u) * 12 + f];
    }

    for (int b = gw; b < B; b += nw) {
        float qv[12];
        #pragma unroll
        for (int f = 0; f < 12; f++) qv[f] = __ldg(&g_q[(size_t)f * B + b]);

        float r[4];
        #pragma unroll
        for (int u = 0; u < 4; u++) {
            float s = cc[u];
            #pragma unroll
            for (int f = 0; f < 12; f++) s = fmaf(a[u][f], qv[f], s);
            r[u] = fmaxf(s, 0.f);
        }
        float4 o;
        o.x = r[0]; o.y = r[1]; o.z = r[2]; o.w = r[3];
        reinterpret_cast<float4*>(out + (size_t)b * 128)[lane] = o;
    }
}

// ---------------- launch ------------------------------------------------
extern "C" void kernel_launch(void* const* d_in, const int* in_sizes, int n_in,
                              void* d_out, int out_size) {
    const float* x  = (const float*)d_in[0];
    const float* p1 = (const float*)d_in[1];
    const float* p2 = (const float*)d_in[2];
    const float* p3 = (const float*)d_in[3];
    const float* fw = (const float*)d_in[4];
    const float* fb = (const float*)d_in[5];
    const float* gm = (const float*)d_in[6];
    const float* bt = (const float*)d_in[7];
    float* out = (float*)d_out;

    int B = in_sizes[0] / 16;

    build_kernel<<<1, 256>>>(p1, p2, p3);
    qforms_kernel<<<592, 256>>>(x, B);
    stats_kernel<<<NPART, 256>>>(B);
    coef_kernel<<<1, 128>>>(fw, fb, gm, bt, B, NPART);
    out_kernel<<<592, 256>>>(out, B);
}

// round 5
// speedup vs baseline: 4.7325x; 4.7325x over previous
#include <cuda_runtime.h>
#include <cstdint>

#define BMAX 524288
#define NPART 148

// ---------------- static device scratch (no allocations) ----------------
__device__ __align__(16) float g_C[136 * 12];   // quadratic-form coeffs, [pair][f]
__device__ float  g_q[(size_t)12 * BMAX];       // per-sample features, SoA [f][b]
__device__ double g_part[NPART * 90];           // per-block stat partials
__device__ double g_ss[90];                     // reduced moments
__device__ __align__(16) float g_A[128 * 12];   // fused FC+BN scale
__device__ float  g_cc[128];                    // fused FC+BN shift

// ---------------- small complex helpers for circuit build ----------------
__device__ __forceinline__ void apply1(float2* amp, int q,
                                       float2 g00, float2 g01,
                                       float2 g10, float2 g11) {
    int bit = 8 >> q; // wire 0 = MSB of 4-bit index
    #pragma unroll
    for (int k = 0; k < 16; k++) {
        if (!(k & bit)) {
            float2 a0 = amp[k], a1 = amp[k | bit];
            amp[k] = make_float2(
                g00.x * a0.x - g00.y * a0.y + g01.x * a1.x - g01.y * a1.y,
                g00.x * a0.y + g00.y * a0.x + g01.x * a1.y + g01.y * a1.x);
            amp[k | bit] = make_float2(
                g10.x * a0.x - g10.y * a0.y + g11.x * a1.x - g11.y * a1.y,
                g10.x * a0.y + g10.y * a0.x + g11.x * a1.y + g11.y * a1.x);
        }
    }
}

__device__ __forceinline__ void cnot_g(float2* amp, int q1, int q2) {
    int b1 = 8 >> q1, b2 = 8 >> q2;
    #pragma unroll
    for (int k = 0; k < 16; k++) {
        if ((k & b1) && !(k & b2)) {
            float2 t = amp[k];
            amp[k] = amp[k | b2];
            amp[k | b2] = t;
        }
    }
}

__device__ __forceinline__ void cz_g(float2* amp, int q1, int q2) {
    int b1 = 8 >> q1, b2 = 8 >> q2;
    #pragma unroll
    for (int k = 0; k < 16; k++) {
        if ((k & b1) && (k & b2)) {
            amp[k].x = -amp[k].x;
            amp[k].y = -amp[k].y;
        }
    }
}

// ---------------- kernel 1: build U matrices + quadratic-form coeffs ----
__global__ void build_kernel(const float* __restrict__ p1,
                             const float* __restrict__ p2,
                             const float* __restrict__ p3) {
    __shared__ float2 sU[3][16][16]; // [circuit][row k][col t]
    const float INVS = 0.7071067811865476f;
    int tid = threadIdx.x;

    if (tid < 48) {
        int c = tid >> 4, t = tid & 15;
        const float* P = (c == 0) ? p1 : ((c == 1) ? p2 : p3);
        float2 amp[16];
        #pragma unroll
        for (int k = 0; k < 16; k++) amp[k] = make_float2(0.f, 0.f);
        amp[t] = make_float2(1.f, 0.f);

        for (int l = 0; l < 2; l++) {
            const float* pl = P + l * 12;
            for (int i = 0; i < 4; i++)
                apply1(amp, i, make_float2(INVS, 0), make_float2(INVS, 0),
                       make_float2(INVS, 0), make_float2(-INVS, 0));
            for (int i = 0; i < 4; i++) {
                float th = pl[i] * 0.5f;
                float cy = cosf(th), sy = sinf(th);
                apply1(amp, i, make_float2(cy, 0), make_float2(-sy, 0),
                       make_float2(sy, 0), make_float2(cy, 0));
                th = pl[4 + i] * 0.5f;
                float cz = cosf(th), sz = sinf(th);
                apply1(amp, i, make_float2(cz, -sz), make_float2(0, 0),
                       make_float2(0, 0), make_float2(cz, sz));
                th = pl[8 + i] * 0.5f;
                float cx = cosf(th), sx = sinf(th);
                apply1(amp, i, make_float2(cx, 0), make_float2(0, -sx),
                       make_float2(0, -sx), make_float2(cx, 0));
            }
            for (int i = 0; i < 4; i++) {
                int bit = 8 >> i;
                for (int k = 0; k < 16; k++)
                    if (k & bit) {
                        float r = amp[k].x;
                        amp[k].x = -amp[k].y;
                        amp[k].y = r;
                    }
            }
            for (int i = 0; i < 3; i++) { cnot_g(amp, i, i + 1); cz_g(amp, i, i + 1); }
            cnot_g(amp, 3, 0);
            cz_g(amp, 3, 0);
        }
        for (int k = 0; k < 16; k++) sU[c][k][t] = amp[k];
    }
    __syncthreads();

    // A_f = Re(U^H D_f U); upper-triangle coeffs (off-diagonals doubled).
    for (int e = tid; e < 1632; e += blockDim.x) {
        int f = e % 12, pr = e / 12;
        int i = 0, rem = pr;
        while (rem >= 16 - i) { rem -= 16 - i; i++; }
        int j = i + rem;
        int c = f >> 2, i0 = f & 3;
        int bit = 8 >> i0;
        float m = 0.f;
        for (int k = 0; k < 16; k++) {
            float2 ui = sU[c][k][i], uj = sU[c][k][j];
            float d = (k & bit) ? -1.f : 1.f;
            m += d * (ui.x * uj.x + ui.y * uj.y);
        }
        g_C[pr * 12 + f] = (i == j) ? m : 2.f * m;
    }
}

// ---------------- kernel 2: per-sample quadratic forms -> q[12] ---------
// 2 samples/thread, float4 coefficient loads, fully unrolled straight-line.
__global__ void __launch_bounds__(256) qforms_kernel(const float* __restrict__ x, int B) {
    __shared__ float4 sC[408]; // 136 pairs x 3 float4
    for (int e = threadIdx.x; e < 408; e += blockDim.x)
        sC[e] = reinterpret_cast<const float4*>(g_C)[e];
    __syncthreads();

    int half = (B + 1) >> 1;
    int idx = blockIdx.x * blockDim.x + threadIdx.x;
    if (idx >= half) return;
    int b0 = idx, b1 = idx + half;
    bool has1 = (b1 < B);

    float xv0[16], xv1[16];
    {
        const float4* xp = reinterpret_cast<const float4*>(x) + (size_t)b0 * 4;
        float4 v;
        v = xp[0]; xv0[0]=v.x; xv0[1]=v.y; xv0[2]=v.z; xv0[3]=v.w;
        v = xp[1]; xv0[4]=v.x; xv0[5]=v.y; xv0[6]=v.z; xv0[7]=v.w;
        v = xp[2]; xv0[8]=v.x; xv0[9]=v.y; xv0[10]=v.z; xv0[11]=v.w;
        v = xp[3]; xv0[12]=v.x; xv0[13]=v.y; xv0[14]=v.z; xv0[15]=v.w;
    }
    {
        const float4* xp = reinterpret_cast<const float4*>(x) + (size_t)(has1 ? b1 : b0) * 4;
        float4 v;
        v = xp[0]; xv1[0]=v.x; xv1[1]=v.y; xv1[2]=v.z; xv1[3]=v.w;
        v = xp[1]; xv1[4]=v.x; xv1[5]=v.y; xv1[6]=v.z; xv1[7]=v.w;
        v = xp[2]; xv1[8]=v.x; xv1[9]=v.y; xv1[10]=v.z; xv1[11]=v.w;
        v = xp[3]; xv1[12]=v.x; xv1[13]=v.y; xv1[14]=v.z; xv1[15]=v.w;
    }

    float n20 = 0.f, n21 = 0.f;
    #pragma unroll
    for (int i = 0; i < 16; i++) { n20 = fmaf(xv0[i], xv0[i], n20); n21 = fmaf(xv1[i], xv1[i], n21); }
    float inv0 = 1.0f / n20, inv1 = 1.0f / n21;

    float q0[12], q1[12];
    #pragma unroll
    for (int f = 0; f < 12; f++) { q0[f] = 0.f; q1[f] = 0.f; }

    const float4* cp = sC;
    #pragma unroll
    for (int i = 0; i < 16; i++) {
        #pragma unroll
        for (int j = i; j < 16; j++) {
            float4 c0 = cp[0], c1 = cp[1], c2 = cp[2];
            cp += 3;
            float p0 = xv0[i] * xv0[j];
            float p1 = xv1[i] * xv1[j];
            q0[0]  = fmaf(c0.x, p0, q0[0]);   q1[0]  = fmaf(c0.x, p1, q1[0]);
            q0[1]  = fmaf(c0.y, p0, q0[1]);   q1[1]  = fmaf(c0.y, p1, q1[1]);
            q0[2]  = fmaf(c0.z, p0, q0[2]);   q1[2]  = fmaf(c0.z, p1, q1[2]);
            q0[3]  = fmaf(c0.w, p0, q0[3]);   q1[3]  = fmaf(c0.w, p1, q1[3]);
            q0[4]  = fmaf(c1.x, p0, q0[4]);   q1[4]  = fmaf(c1.x, p1, q1[4]);
            q0[5]  = fmaf(c1.y, p0, q0[5]);   q1[5]  = fmaf(c1.y, p1, q1[5]);
            q0[6]  = fmaf(c1.z, p0, q0[6]);   q1[6]  = fmaf(c1.z, p1, q1[6]);
            q0[7]  = fmaf(c1.w, p0, q0[7]);   q1[7]  = fmaf(c1.w, p1, q1[7]);
            q0[8]  = fmaf(c2.x, p0, q0[8]);   q1[8]  = fmaf(c2.x, p1, q1[8]);
            q0[9]  = fmaf(c2.y, p0, q0[9]);   q1[9]  = fmaf(c2.y, p1, q1[9]);
            q0[10] = fmaf(c2.z, p0, q0[10]);  q1[10] = fmaf(c2.z, p1, q1[10]);
            q0[11] = fmaf(c2.w, p0, q0[11]);  q1[11] = fmaf(c2.w, p1, q1[11]);
        }
    }

    #pragma unroll
    for (int f = 0; f < 12; f++)
        g_q[(size_t)f * B + b0] = q0[f] * inv0;
    if (has1) {
        #pragma unroll
        for (int f = 0; f < 12; f++)
            g_q[(size_t)f * B + b1] = q1[f] * inv1;
    }
}

// ---------------- kernel 3: batch moments (deterministic tree) ----------
__global__ void stats_kernel(int B) {
    float acc[90];
    #pragma unroll
    for (int k = 0; k < 90; k++) acc[k] = 0.f;

    int stride = gridDim.x * blockDim.x;
    for (int b = blockIdx.x * blockDim.x + threadIdx.x; b < B; b += stride) {
        float qv[12];
        #pragma unroll
        for (int f = 0; f < 12; f++) qv[f] = g_q[(size_t)f * B + b];
        #pragma unroll
        for (int f = 0; f < 12; f++) acc[f] += qv[f];
        int k = 12;
        #pragma unroll
        for (int f = 0; f < 12; f++)
            #pragma unroll
            for (int g = f; g < 12; g++)
                acc[k++] += qv[f] * qv[g];
    }
    #pragma unroll
    for (int k = 0; k < 90; k++)
        #pragma unroll
        for (int off = 16; off > 0; off >>= 1)
            acc[k] += __shfl_down_sync(0xffffffffu, acc[k], off);

    __shared__ float swarp[8][90];
    int warp = threadIdx.x >> 5, lane = threadIdx.x & 31;
    if (lane == 0)
        for (int k = 0; k < 90; k++) swarp[warp][k] = acc[k];
    __syncthreads();

    int nw = blockDim.x >> 5;
    for (int k = threadIdx.x; k < 90; k += blockDim.x) {
        double s = 0.0;
        for (int w = 0; w < nw; w++) s += (double)swarp[w][k];
        g_part[blockIdx.x * 90 + k] = s;
    }
}

// ---------------- kernel 4a: reduce per-block partials (light regs) -----
__global__ void __launch_bounds__(768) reduce_kernel(int npart) {
    __shared__ double sp[768];
    int t = threadIdx.x;
    double a = 0.0;
    if (t < 720) {
        int k = t >> 3, s = t & 7;
        for (int p = s; p < npart; p += 8)
            a += g_part[p * 90 + k];
    }
    sp[t] = a;
    __syncthreads();
    if (t < 90) {
        double s = 0.0;
        #pragma unroll
        for (int u = 0; u < 8; u++) s += sp[t * 8 + u];
        g_ss[t] = s;
    }
}

// ---------------- kernel 4b: fold BN into affine coeffs (128 thr) -------
__global__ void coef_kernel(const float* __restrict__ fw,
                            const float* __restrict__ fb,
                            const float* __restrict__ gamma,
                            const float* __restrict__ beta,
                            int B) {
    __shared__ double ss[90];
    int t = threadIdx.x;
    for (int k = t; k < 90; k += blockDim.x) ss[k] = g_ss[k];
    __syncthreads();

    int j = t;
    if (j < 128) {
        double invB = 1.0 / (double)B;
        double mean[12], w[12];
        for (int f = 0; f < 12; f++) {
            mean[f] = ss[f] * invB;
            w[f] = (double)fw[j * 12 + f];
        }
        double mu = (double)fb[j];
        for (int f = 0; f < 12; f++) mu += w[f] * mean[f];
        double var = 0.0;
        for (int f = 0; f < 12; f++)
            for (int g = 0; g < 12; g++) {
                int a = f < g ? f : g, bb = f < g ? g : f;
                double e2 = ss[12 + a * 12 - (a * (a + 1)) / 2 + bb] * invB;
                var += w[f] * w[g] * (e2 - mean[f] * mean[g]);
            }
        double s = (double)gamma[j] * rsqrt(var + 1e-5);
        for (int f = 0; f < 12; f++) g_A[j * 12 + f] = (float)(s * w[f]);
        g_cc[j] = (float)(s * ((double)fb[j] - mu) + (double)beta[j]);
    }
}

// ---------------- kernel 5: fused FC+BN+ReLU output ---------------------
__global__ void out_kernel(float* __restrict__ out, int B) {
    int lane = threadIdx.x & 31;
    int gw = (blockIdx.x * blockDim.x + threadIdx.x) >> 5;
    int nw = (gridDim.x * blockDim.x) >> 5;
    int j0 = lane * 4;

    float a[4][12], cc[4];
    #pragma unroll
    for (int u = 0; u < 4; u++) {
        cc[u] = g_cc[j0 + u];
        #pragma unroll
        for (int f = 0; f < 12; f++) a[u][f] = g_A[(j0 + u) * 12 + f];
    }

    for (int b = gw; b < B; b += nw) {
        float qv[12];
        #pragma unroll
        for (int f = 0; f < 12; f++) qv[f] = __ldg(&g_q[(size_t)f * B + b]);

        float r[4];
        #pragma unroll
        for (int u = 0; u < 4; u++) {
            float s = cc[u];
            #pragma unroll
            for (int f = 0; f < 12; f++) s = fmaf(a[u][f], qv[f], s);
            r[u] = fmaxf(s, 0.f);
        }
        float4 o;
        o.x = r[0]; o.y = r[1]; o.z = r[2]; o.w = r[3];
        __stcs(reinterpret_cast<float4*>(out + (size_t)b * 128) + lane, o);
    }
}

// ---------------- launch ------------------------------------------------
extern "C" void kernel_launch(void* const* d_in, const int* in_sizes, int n_in,
                              void* d_out, int out_size) {
    const float* x  = (const float*)d_in[0];
    const float* p1 = (const float*)d_in[1];
    const float* p2 = (const float*)d_in[2];
    const float* p3 = (const float*)d_in[3];
    const float* fw = (const float*)d_in[4];
    const float* fb = (const float*)d_in[5];
    const float* gm = (const float*)d_in[6];
    const float* bt = (const float*)d_in[7];
    float* out = (float*)d_out;

    int B = in_sizes[0] / 16;
    int half = (B + 1) >> 1;
    int qblocks = (half + 255) / 256;

    build_kernel<<<1, 256>>>(p1, p2, p3);
    qforms_kernel<<<qblocks, 256>>>(x, B);
    stats_kernel<<<NPART, 256>>>(B);
    reduce_kernel<<<1, 768>>>(NPART);
    coef_kernel<<<1, 128>>>(fw, fb, gm, bt, B);
    out_kernel<<<592, 256>>>(out, B);
}